// round 5
// baseline (speedup 1.0000x reference)
#include <cuda_runtime.h>
#include <math.h>

// Problem constants (match reference)
#define FF       20
#define V_FIELD  5000
#define TOTALV   (FF * V_FIELD)     // 100000
#define DD       64
#define BB       8192
#define NPAIRS   190

// Schedule: 10 groups of 19 pairs. Group is the SLOW grid axis so concurrent
// CTAs share the same ~49MB L2 working set (19 pairs x 2 x 1.28MB regions).
#define PPG              19
#define NGROUPS          10
#define WARPS_PER_BLOCK  8
#define WS               2                       // samples per warp
#define SAMPLES_PER_BLOCK (WARPS_PER_BLOCK * WS) // 16
#define NCHUNKS          (BB / SAMPLES_PER_BLOCK) // 512

// Per-(group, sample) partial sums (interaction + this group's 2 linear terms).
// Every slot written every launch -> deterministic, no memset needed.
__device__ float        g_part[NGROUPS * BB];
// Per-chunk completion counters. Zero-initialized at module load; the winning
// (10th) block resets its counter to 0, so every graph replay starts from 0.
__device__ unsigned int g_cnt[NCHUNKS];

// Single fused kernel: grid = (chunk, group). Each warp owns WS samples; per
// sample it loops the group's 19 pairs (two coalesced 256B row loads + 2 FMAs
// per lane each) plus the group's 2 linear-term gathers, warp-reduces, and
// stores one partial. The last block to finish a chunk (threadfence +
// atomic counter) re-reads the 10 partials in fixed order, adds bias, applies
// sigmoid, and writes the output — finalize overlaps remaining gather work.
__global__ void __launch_bounds__(WARPS_PER_BLOCK * 32)
ffm_fused(const int* __restrict__ x, const float* __restrict__ W,
          const float* __restrict__ Wl, const float* __restrict__ bias,
          float* __restrict__ out) {
    __shared__ int sI[PPG], sJ[PPG];
    __shared__ bool amLast;
    const int g = blockIdx.y;
    if (threadIdx.x < PPG) {
        int p = g * PPG + threadIdx.x;
        int i = 0, rem = p;
        while (rem >= FF - 1 - i) { rem -= FF - 1 - i; i++; }
        sI[threadIdx.x] = i;
        sJ[threadIdx.x] = i + 1 + rem;
    }
    __syncthreads();

    const int lane = threadIdx.x & 31;
    const int w    = threadIdx.x >> 5;
    const int sbase = blockIdx.x * SAMPLES_PER_BLOCK + w * WS;
    const float2* __restrict__ W2 = (const float2*)W;

    for (int ss = 0; ss < WS; ss++) {
        const int s = sbase + ss;
        // Preload this sample's full index row across lanes (broadcast via shfl).
        int xv = 0;
        if (lane < FF) xv = x[s * FF + lane];

        // Linear term for this group's two fields (2g, 2g+1) on lanes 0-1.
        float acc = 0.f;
        {
            const int xf = __shfl_sync(0xffffffffu, xv, 2 * g + lane);
            if (lane < 2)
                acc = __ldg(&Wl[(2 * g + lane) * V_FIELD + xf]);
        }

        #pragma unroll
        for (int q = 0; q < PPG; q++) {
            const int i = sI[q];
            const int j = sJ[q];
            const int xi = __shfl_sync(0xffffffffu, xv, i);
            const int xj = __shfl_sync(0xffffffffu, xv, j);
            // a = W[j, i*V_FIELD + xi, :], b = W[i, j*V_FIELD + xj, :]
            const size_t ra = ((size_t)j * TOTALV + (size_t)(i * V_FIELD + xi)) * (DD / 2);
            const size_t rb = ((size_t)i * TOTALV + (size_t)(j * V_FIELD + xj)) * (DD / 2);
            const float2 av = __ldg(&W2[ra + lane]);
            const float2 bv = __ldg(&W2[rb + lane]);
            acc = fmaf(av.x, bv.x, acc);
            acc = fmaf(av.y, bv.y, acc);
        }
        #pragma unroll
        for (int o = 16; o; o >>= 1)
            acc += __shfl_xor_sync(0xffffffffu, acc, o);
        if (lane == 0)
            g_part[g * BB + s] = acc;
    }

    // ---- last-block-per-chunk finalize ----
    __syncthreads();  // all warps' g_part stores issued
    if (threadIdx.x == 0) {
        __threadfence();  // make this block's partials visible chip-wide
        unsigned int old = atomicAdd(&g_cnt[blockIdx.x], 1u);
        amLast = (old == NGROUPS - 1);
    }
    __syncthreads();
    if (amLast) {
        if (threadIdx.x < SAMPLES_PER_BLOCK) {
            const int s = blockIdx.x * SAMPLES_PER_BLOCK + threadIdx.x;
            float v = bias[0];
            #pragma unroll
            for (int gg = 0; gg < NGROUPS; gg++)
                v += g_part[gg * BB + s];
            out[s] = 1.f / (1.f + __expf(-v));
        }
        if (threadIdx.x == 0)
            g_cnt[blockIdx.x] = 0;  // reset for next graph replay
    }
}

extern "C" void kernel_launch(void* const* d_in, const int* in_sizes, int n_in,
                              void* d_out, int out_size) {
    const int*   x    = (const int*)d_in[0];
    const float* W    = (const float*)d_in[1];
    const float* Wl   = (const float*)d_in[2];
    const float* bias = (const float*)d_in[3];
    float*       out  = (float*)d_out;

    dim3 grid(NCHUNKS, NGROUPS);
    ffm_fused<<<grid, WARPS_PER_BLOCK * 32>>>(x, W, Wl, bias, out);
}

// round 6
// speedup vs baseline: 1.1070x; 1.1070x over previous
#include <cuda_runtime.h>
#include <math.h>

// Problem constants (match reference)
#define FF       20
#define V_FIELD  5000
#define TOTALV   (FF * V_FIELD)     // 100000
#define DD       64
#define BB       8192
#define NPAIRS   190

// Schedule: 10 groups of 19 pairs. Group is the SLOW grid axis so concurrent
// CTAs share the same ~49MB L2 working set (19 pairs x 2 x 1.28MB regions);
// DRAM then sees each unique row roughly once (measured: ~429MB ~= floor).
#define PPG              19
#define NGROUPS          10
#define WARPS_PER_BLOCK  8
#define WS               2                       // samples per warp (interleaved)
#define SAMPLES_PER_BLOCK (WARPS_PER_BLOCK * WS) // 16
#define NCHUNKS          (BB / SAMPLES_PER_BLOCK) // 512

// Per-(group, sample) partial sums (interaction + this group's 2 linear terms).
// Every slot written every launch -> deterministic, no memset needed.
__device__ float g_part[NGROUPS * BB];

// Main gather/dot kernel: grid = (chunk, group). Each warp owns 2 samples,
// processed INTERLEAVED inside the pair loop (doubles outstanding loads).
// Per pair: 4 coalesced 256B row loads (float2/lane) + 16 FMAs. Per-pair base
// offsets precomputed in smem to cut address ALU. Group g also gathers the
// linear term for its 2 fields. One warp reduction + one store per (sample).
__global__ void __launch_bounds__(WARPS_PER_BLOCK * 32, 3)
ffm_pairs(const int* __restrict__ x, const float* __restrict__ W,
          const float* __restrict__ Wl) {
    __shared__ int      sI[PPG], sJ[PPG];
    __shared__ unsigned cA[PPG], cB[PPG];   // float2-element base offsets
    const int g = blockIdx.y;
    if (threadIdx.x < PPG) {
        int p = g * PPG + threadIdx.x;
        int i = 0, rem = p;
        while (rem >= FF - 1 - i) { rem -= FF - 1 - i; i++; }
        const int j = i + 1 + rem;
        sI[threadIdx.x] = i;
        sJ[threadIdx.x] = j;
        // a = W[j, i*V_FIELD + xi], b = W[i, j*V_FIELD + xj]; offsets in float2 units
        cA[threadIdx.x] = (unsigned)(j * TOTALV + i * V_FIELD) * (DD / 2);
        cB[threadIdx.x] = (unsigned)(i * TOTALV + j * V_FIELD) * (DD / 2);
    }
    __syncthreads();

    const int lane = threadIdx.x & 31;
    const int w    = threadIdx.x >> 5;
    const int s0   = blockIdx.x * SAMPLES_PER_BLOCK + w * WS;
    const int s1   = s0 + 1;
    const float2* __restrict__ W2 = (const float2*)W;

    // Preload both samples' index rows across lanes (broadcast via shfl).
    int xv0 = 0, xv1 = 0;
    if (lane < FF) {
        xv0 = x[s0 * FF + lane];
        xv1 = x[s1 * FF + lane];
    }

    // Linear term for this group's two fields (2g, 2g+1) on lanes 0-1.
    float acc0 = 0.f, acc1 = 0.f;
    {
        const int xf0 = __shfl_sync(0xffffffffu, xv0, 2 * g + lane);
        const int xf1 = __shfl_sync(0xffffffffu, xv1, 2 * g + lane);
        if (lane < 2) {
            acc0 = __ldg(&Wl[(2 * g + lane) * V_FIELD + xf0]);
            acc1 = __ldg(&Wl[(2 * g + lane) * V_FIELD + xf1]);
        }
    }

    #pragma unroll
    for (int q = 0; q < PPG; q++) {
        const int si = sI[q], sj = sJ[q];
        const unsigned ca = cA[q], cb = cB[q];
        const int xi0 = __shfl_sync(0xffffffffu, xv0, si);
        const int xj0 = __shfl_sync(0xffffffffu, xv0, sj);
        const int xi1 = __shfl_sync(0xffffffffu, xv1, si);
        const int xj1 = __shfl_sync(0xffffffffu, xv1, sj);
        const float2 av0 = __ldg(W2 + ca + (unsigned)xi0 * (DD / 2) + lane);
        const float2 bv0 = __ldg(W2 + cb + (unsigned)xj0 * (DD / 2) + lane);
        const float2 av1 = __ldg(W2 + ca + (unsigned)xi1 * (DD / 2) + lane);
        const float2 bv1 = __ldg(W2 + cb + (unsigned)xj1 * (DD / 2) + lane);
        acc0 = fmaf(av0.x, bv0.x, acc0);
        acc0 = fmaf(av0.y, bv0.y, acc0);
        acc1 = fmaf(av1.x, bv1.x, acc1);
        acc1 = fmaf(av1.y, bv1.y, acc1);
    }
    #pragma unroll
    for (int o = 16; o; o >>= 1) {
        acc0 += __shfl_xor_sync(0xffffffffu, acc0, o);
        acc1 += __shfl_xor_sync(0xffffffffu, acc1, o);
    }
    if (lane == 0) {
        g_part[g * BB + s0] = acc0;
        g_part[g * BB + s1] = acc1;
    }
}

// Finalize: thread-per-sample, 10 unrolled coalesced partial loads (MLP=10)
// + bias + sigmoid. 64 blocks x 128 threads to spread across SMs.
__global__ void __launch_bounds__(128)
ffm_final(const float* __restrict__ bias, float* __restrict__ out) {
    const int s = blockIdx.x * blockDim.x + threadIdx.x;
    if (s >= BB) return;
    float v = bias[0];
    #pragma unroll
    for (int gg = 0; gg < NGROUPS; gg++)
        v += __ldg(&g_part[gg * BB + s]);
    out[s] = 1.f / (1.f + __expf(-v));
}

extern "C" void kernel_launch(void* const* d_in, const int* in_sizes, int n_in,
                              void* d_out, int out_size) {
    const int*   x    = (const int*)d_in[0];
    const float* W    = (const float*)d_in[1];
    const float* Wl   = (const float*)d_in[2];
    const float* bias = (const float*)d_in[3];
    float*       out  = (float*)d_out;

    dim3 grid(NCHUNKS, NGROUPS);
    ffm_pairs<<<grid, WARPS_PER_BLOCK * 32>>>(x, W, Wl);
    ffm_final<<<BB / 128, 128>>>(bias, out);
}

// round 7
// speedup vs baseline: 1.1806x; 1.0664x over previous
#include <cuda_runtime.h>
#include <math.h>

// Problem constants (match reference)
#define FF       20
#define V_FIELD  5000
#define TOTALV   (FF * V_FIELD)     // 100000
#define DD       64
#define BB       8192
#define NPAIRS   190

#define WARPS_PER_BLOCK  8
#define NBLOCKS          (BB / WARPS_PER_BLOCK)  // 1024 -> one full wave

// Sample-major single kernel: one warp per sample walks ALL 190 pairs in a
// fixed order. All 8192 warps fit in one wave, progress in rough lockstep, so
// at any instant the chip touches a narrow band of pair regions (~50MB << L2)
// -- same L2 confinement as group-blocking, but temporal. No partials, no
// second kernel: warp reduces, adds linear+bias, sigmoid, stores out[s].
__global__ void __launch_bounds__(WARPS_PER_BLOCK * 32)
ffm_all(const int* __restrict__ x, const float* __restrict__ W,
        const float* __restrict__ Wl, const float* __restrict__ bias,
        float* __restrict__ out) {
    // Pair metadata: {i, j, baseA, baseB} per pair; baseX in float2 units.
    __shared__ int4 meta[NPAIRS];
    for (int p = threadIdx.x; p < NPAIRS; p += blockDim.x) {
        int i = 0, rem = p;
        while (rem >= FF - 1 - i) { rem -= FF - 1 - i; i++; }
        const int j = i + 1 + rem;
        // a = W[j, i*V_FIELD + xi], b = W[i, j*V_FIELD + xj]
        meta[p] = make_int4(i, j,
                            (j * TOTALV + i * V_FIELD) * (DD / 2),
                            (i * TOTALV + j * V_FIELD) * (DD / 2));
    }
    __syncthreads();

    const int lane = threadIdx.x & 31;
    const int w    = threadIdx.x >> 5;
    const int s    = blockIdx.x * WARPS_PER_BLOCK + w;
    const float2* __restrict__ W2 = (const float2*)W;

    // Index row across lanes; lanes < FF also seed the linear term.
    int   xv  = 0;
    float acc = 0.f;
    if (lane < FF) {
        xv  = x[s * FF + lane];
        acc = __ldg(&Wl[lane * V_FIELD + xv]);
    }

    // 190 pairs, unrolled x5 -> up to 10 outstanding 256B row loads per warp.
    #pragma unroll 5
    for (int q = 0; q < NPAIRS; q++) {
        const int4 m = meta[q];
        const int xi = __shfl_sync(0xffffffffu, xv, m.x);
        const int xj = __shfl_sync(0xffffffffu, xv, m.y);
        const float2 av = __ldg(W2 + (unsigned)(m.z + xi * (DD / 2)) + lane);
        const float2 bv = __ldg(W2 + (unsigned)(m.w + xj * (DD / 2)) + lane);
        acc = fmaf(av.x, bv.x, acc);
        acc = fmaf(av.y, bv.y, acc);
    }

    #pragma unroll
    for (int o = 16; o; o >>= 1)
        acc += __shfl_xor_sync(0xffffffffu, acc, o);
    if (lane == 0) {
        const float z = acc + bias[0];
        out[s] = 1.f / (1.f + __expf(-z));
    }
}

extern "C" void kernel_launch(void* const* d_in, const int* in_sizes, int n_in,
                              void* d_out, int out_size) {
    const int*   x    = (const int*)d_in[0];
    const float* W    = (const float*)d_in[1];
    const float* Wl   = (const float*)d_in[2];
    const float* bias = (const float*)d_in[3];
    float*       out  = (float*)d_out;

    ffm_all<<<NBLOCKS, WARPS_PER_BLOCK * 32>>>(x, W, Wl, bias, out);
}